// round 7
// baseline (speedup 1.0000x reference)
#include <cuda_runtime.h>
#include <stdint.h>
#include <math.h>

// Problem constants
#define Bn 4096
#define Gn 256
#define NCOLS 640

// Scratch (device globals)
__device__ float g_P2tab[20 * 128 * 16 * 32];  // [chunk][pair][combo][c] 5.24 MB
__device__ float g_Hall[Bn * NCOLS];           // 10.5 MB
__device__ float g_NumConn[Bn];

// ---------------------------------------------------------------------------
// Fused precompute: P2[pair, t1*4+t2, c] = emb[t1].W[2p rows] + emb[t2].W[2p+1 rows]
// grid 128 (pair), block 640 (col)
// ---------------------------------------------------------------------------
__global__ __launch_bounds__(640) void precompute_P2(
        const float* __restrict__ emb,
        const float* __restrict__ pw1, const float* __restrict__ dw1,
        const float* __restrict__ nw1, const float* __restrict__ cw1) {
    __shared__ float embS[128];
    const int p = blockIdx.x, c = threadIdx.x;
    if (c < 128) embS[c] = emb[c];
    __syncthreads();

    const float* src; int stride;
    if      (c < 128) { src = pw1 + c;         stride = 128; }
    else if (c < 256) { src = dw1 + (c - 128); stride = 128; }
    else if (c < 384) { src = nw1 + (c - 256); stride = 128; }
    else              { src = cw1 + (c - 384); stride = 256; }
    src += (size_t)(2 * p) * 32 * stride;
    const float* src2 = src + 32 * stride;

    float a[4] = {0.f, 0.f, 0.f, 0.f};
    float b[4] = {0.f, 0.f, 0.f, 0.f};
#pragma unroll
    for (int k = 0; k < 32; k += 4) {
        float w0 = src[(k + 0) * stride],  w1 = src[(k + 1) * stride];
        float w2 = src[(k + 2) * stride],  w3 = src[(k + 3) * stride];
        float v0 = src2[(k + 0) * stride], v1 = src2[(k + 1) * stride];
        float v2 = src2[(k + 2) * stride], v3 = src2[(k + 3) * stride];
#pragma unroll
        for (int t = 0; t < 4; t++) {
            a[t] += embS[t*32+k] * w0 + embS[t*32+k+1] * w1 + embS[t*32+k+2] * w2 + embS[t*32+k+3] * w3;
            b[t] += embS[t*32+k] * v0 + embS[t*32+k+1] * v1 + embS[t*32+k+2] * v2 + embS[t*32+k+3] * v3;
        }
    }
    const int ch = c >> 5, cc = c & 31;
    float* base = g_P2tab + ((size_t)(ch * 128 + p) * 16) * 32 + cc;
#pragma unroll
    for (int t1 = 0; t1 < 4; t1++)
#pragma unroll
        for (int t2 = 0; t2 < 4; t2++)
            base[(t1 * 4 + t2) * 32] = a[t1] + b[t2];
}

// ---------------------------------------------------------------------------
// cp.async helpers
// ---------------------------------------------------------------------------
__device__ __forceinline__ void cp_async16(unsigned int saddr, const void* gptr) {
    asm volatile("cp.async.cg.shared.global [%0], [%1], 16;\n" :: "r"(saddr), "l"(gptr));
}
__device__ __forceinline__ void cp_commit() {
    asm volatile("cp.async.commit_group;\n");
}

// ---------------------------------------------------------------------------
// Fused main: Hall accumulate (smem) + conn reduction (HBM), cp.async
// double-buffered tiles so HBM streaming never pauses.
// grid 640 = 64 batch-groups x 10 col-groups; cg<8 blocks own 8 conn rows.
// ---------------------------------------------------------------------------
__global__ __launch_bounds__(512, 1) void fused_main(
        const float* __restrict__ conn, const int* __restrict__ gate_types) {
    extern __shared__ float sC[];
    // layout: tile[2][16384] | tpackS[1024] | ws[16]
    unsigned* tpackS = (unsigned*)(sC + 32768);
    float*    ws     = sC + 32768 + 1024;

    const int tid = threadIdx.x;
    const int grp = blockIdx.x / 10;
    const int cg  = blockIdx.x % 10;
    const int b0  = grp * 64;
    const bool doConn = (cg < 8);

    const unsigned int smemBase = (unsigned int)__cvta_generic_to_shared(sC);

    // prefetch subtile 0
    {
        const int chunk = cg * 2;
        const float4* srcT = (const float4*)(g_P2tab + ((size_t)(chunk * 128) * 16) * 32);
        unsigned int d = smemBase + tid * 16;
#pragma unroll
        for (int i = 0; i < 8; i++)
            cp_async16(d + i * 512 * 16, srcT + tid + i * 512);
        cp_commit();
    }

    // pack combos: 8 pairs (4 bits each) per u32, 16 words per batch
    for (int i = tid; i < 1024; i += 512) {
        int blc = i >> 4, w = i & 15;
        const int4* gt = (const int4*)(gate_types + (size_t)(b0 + blc) * Gn + w * 16);
        int4 A = gt[0], B4 = gt[1], C = gt[2], D = gt[3];
        unsigned u = 0;
        u |= (unsigned)(A.x * 4 + A.y);
        u |= (unsigned)(A.z * 4 + A.w) << 4;
        u |= (unsigned)(B4.x * 4 + B4.y) << 8;
        u |= (unsigned)(B4.z * 4 + B4.w) << 12;
        u |= (unsigned)(C.x * 4 + C.y) << 16;
        u |= (unsigned)(C.z * 4 + C.w) << 20;
        u |= (unsigned)(D.x * 4 + D.y) << 24;
        u |= (unsigned)(D.z * 4 + D.w) << 28;
        tpackS[i] = u;
    }

    const int bl = tid >> 3;   // local batch 0..63
    const int c4 = tid & 7;    // float4 col slot

    float ax = 0.f, ay = 0.f, az = 0.f, aw = 0.f;

#pragma unroll
    for (int s = 0; s < 8; s++) {
        // prefetch next subtile into the other buffer
        if (s < 7) {
            const int ns = s + 1;
            const int chunk = cg * 2 + (ns >> 2);
            const int pb    = ns & 3;
            const float4* srcT = (const float4*)(g_P2tab +
                                 ((size_t)(chunk * 128 + pb * 32) * 16) * 32);
            unsigned int d = smemBase + (ns & 1) * 65536 + tid * 16;
#pragma unroll
            for (int i = 0; i < 8; i++)
                cp_async16(d + i * 512 * 16, srcT + tid + i * 512);
            cp_commit();
            asm volatile("cp.async.wait_group 1;\n");
        } else {
            asm volatile("cp.async.wait_group 0;\n");
        }
        __syncthreads();  // current tile visible to all; prev buffer free

        const float* tileS = sC + (s & 1) * 16384;
        const int pb = s & 3;

        const int row = b0 + ((cg < 8) ? cg : 0) * 8 + s;
        const float4* cp4 = (const float4*)conn + ((size_t)row << 14) + tid;
        float rsum = 0.f;

#pragma unroll
        for (int half = 0; half < 4; half++) {
            const unsigned word = tpackS[bl * 16 + pb * 4 + half];

            float4 q0, q1, q2, q3, q4, q5, q6, q7;
            if (doConn) {
                q0 = cp4[(half * 8 + 0) * 512];
                q1 = cp4[(half * 8 + 1) * 512];
                q2 = cp4[(half * 8 + 2) * 512];
                q3 = cp4[(half * 8 + 3) * 512];
                q4 = cp4[(half * 8 + 4) * 512];
                q5 = cp4[(half * 8 + 5) * 512];
                q6 = cp4[(half * 8 + 6) * 512];
                q7 = cp4[(half * 8 + 7) * 512];
            } else {
                q0 = q1 = q2 = q3 = q4 = q5 = q6 = q7 = make_float4(0.f, 0.f, 0.f, 0.f);
            }
#pragma unroll
            for (int i = 0; i < 8; i++) {
                int combo = (int)((word >> (i * 4)) & 15u);
                const float4 v = *(const float4*)&tileS[((half * 8 + i) * 16 + combo) * 32 + c4 * 4];
                ax += v.x; ay += v.y; az += v.z; aw += v.w;
            }
            rsum += (((q0.x + q0.y) + (q0.z + q0.w)) + ((q1.x + q1.y) + (q1.z + q1.w)))
                  + (((q2.x + q2.y) + (q2.z + q2.w)) + ((q3.x + q3.y) + (q3.z + q3.w)))
                  + (((q4.x + q4.y) + (q4.z + q4.w)) + ((q5.x + q5.y) + (q5.z + q5.w)))
                  + (((q6.x + q6.y) + (q6.z + q6.w)) + ((q7.x + q7.y) + (q7.z + q7.w)));
        }

        if (s == 3) {
            float4 rr; rr.x = ax; rr.y = ay; rr.z = az; rr.w = aw;
            *(float4*)(g_Hall + (size_t)(b0 + bl) * NCOLS + (cg * 2) * 32 + c4 * 4) = rr;
            ax = ay = az = aw = 0.f;
        }
        if (s == 7) {
            float4 rr; rr.x = ax; rr.y = ay; rr.z = az; rr.w = aw;
            *(float4*)(g_Hall + (size_t)(b0 + bl) * NCOLS + (cg * 2 + 1) * 32 + c4 * 4) = rr;
        }

        if (doConn) {
#pragma unroll
            for (int o = 16; o; o >>= 1) rsum += __shfl_xor_sync(0xffffffffu, rsum, o);
            if ((tid & 31) == 0) ws[tid >> 5] = rsum;
        }
        __syncthreads();  // ws ready; current buffer reads done before reuse
        if (doConn && tid == 0) {
            float t = 0.f;
#pragma unroll
            for (int i = 0; i < 16; i++) t += ws[i];
            g_NumConn[row] = t;
        }
    }
}

// ---------------------------------------------------------------------------
// Finalize v2: 512 blocks x 256 threads, 8 batches/block, vectorized.
// ---------------------------------------------------------------------------
__device__ __forceinline__ float softplusf_(float x) {
    return (x > 20.f) ? x : log1pf(expf(x));
}
__device__ __forceinline__ float sigmoidf_(float x) {
    return 1.f / (1.f + expf(-x));
}

// smem layout (floats)
#define F_H1S   0        // 2048 (8 x 256)
#define F_CW2T  2048     // 8192
#define F_BIAS  10240    // 768
#define F_CB1   11008    // 256
#define F_WIN   11264    // 3072
#define F_REDA  14336    // 64 (8 x 8)
#define F_PACC  14400    // 1024 (8 x 128)
#define F_RED2  15424    // 32
#define F_TOT   15456

__global__ __launch_bounds__(256) void finalize_kernel(
        const int* __restrict__ gate_types,
        const float* __restrict__ inputs,
        const float* __restrict__ outputs,
        const float* __restrict__ pb1, const float* __restrict__ pw2, const float* __restrict__ pb2,
        const float* __restrict__ db1, const float* __restrict__ dw2, const float* __restrict__ db2,
        const float* __restrict__ nb1, const float* __restrict__ nw2, const float* __restrict__ nb2,
        const float* __restrict__ cw1, const float* __restrict__ cb1,
        const float* __restrict__ cw2, const float* __restrict__ cb2,
        const float* __restrict__ cw3, const float* __restrict__ cb3,
        float* __restrict__ out) {
    extern __shared__ float sD[];
    float* h1s   = sD + F_H1S;
    float* cw2t  = sD + F_CW2T;
    float* biasS = sD + F_BIAS;
    float* cb1S  = sD + F_CB1;
    float* winS  = sD + F_WIN;
    float* redA  = sD + F_REDA;
    float* pacc  = sD + F_PACC;
    float* red2  = sD + F_RED2;

    const int tid  = threadIdx.x;
    const int lane = tid & 31, warp = tid >> 5;
    const int gb   = blockIdx.x * 8;

    if (tid < 128) {
        biasS[tid]       = pb1[tid];
        biasS[128 + tid] = db1[tid];
        biasS[256 + tid] = nb1[tid];
        biasS[384 + tid] = pw2[tid];
        biasS[512 + tid] = dw2[tid];
        biasS[640 + tid] = nw2[tid];
    }
    cb1S[tid] = cb1[tid];
    const float* winsrc = cw1 + 8192 * 256;
    for (int i = tid; i < 3072; i += 256) winS[i] = winsrc[i];
    __syncthreads();

    // ---- phase 1: warp per batch, all float4 ----
    {
        const int bl = warp;           // 0..7
        const int b  = gb + bl;
        const float4* H4  = (const float4*)(g_Hall + (size_t)b * NCOLS);
        const float4* B4  = (const float4*)biasS;
        const float4* CB4 = (const float4*)cb1S;
        const float4* W4  = (const float4*)winS;

        float4 h, bb, ww;
        h = H4[lane];        bb = B4[lane];        ww = B4[96 + lane];
        float vp = fmaxf(h.x + bb.x, 0.f) * ww.x + fmaxf(h.y + bb.y, 0.f) * ww.y
                 + fmaxf(h.z + bb.z, 0.f) * ww.z + fmaxf(h.w + bb.w, 0.f) * ww.w;
        h = H4[32 + lane];   bb = B4[32 + lane];   ww = B4[128 + lane];
        float vd = fmaxf(h.x + bb.x, 0.f) * ww.x + fmaxf(h.y + bb.y, 0.f) * ww.y
                 + fmaxf(h.z + bb.z, 0.f) * ww.z + fmaxf(h.w + bb.w, 0.f) * ww.w;
        h = H4[64 + lane];   bb = B4[64 + lane];   ww = B4[160 + lane];
        float vn = fmaxf(h.x + bb.x, 0.f) * ww.x + fmaxf(h.y + bb.y, 0.f) * ww.y
                 + fmaxf(h.z + bb.z, 0.f) * ww.z + fmaxf(h.w + bb.w, 0.f) * ww.w;

        const int4* tq = (const int4*)(gate_types + (size_t)b * Gn);
        int4 ta = tq[lane * 2], tb = tq[lane * 2 + 1];
        float c0 = (float)((ta.x == 0) + (ta.y == 0) + (ta.z == 0) + (ta.w == 0)
                         + (tb.x == 0) + (tb.y == 0) + (tb.z == 0) + (tb.w == 0));
        float c1 = (float)((ta.x == 1) + (ta.y == 1) + (ta.z == 1) + (ta.w == 1)
                         + (tb.x == 1) + (tb.y == 1) + (tb.z == 1) + (tb.w == 1));
        float c2 = (float)((ta.x == 2) + (ta.y == 2) + (ta.z == 2) + (ta.w == 2)
                         + (tb.x == 2) + (tb.y == 2) + (tb.z == 2) + (tb.w == 2));
        float c3 = (float)((ta.x == 3) + (ta.y == 3) + (ta.z == 3) + (ta.w == 3)
                         + (tb.x == 3) + (tb.y == 3) + (tb.z == 3) + (tb.w == 3));

        float xv = 0.f;
        if (lane < 8)       xv = inputs[b * 8 + lane];
        else if (lane < 12) xv = outputs[b * 4 + lane - 8];

#pragma unroll
        for (int m = 0; m < 2; m++) {
            float4 ha = H4[96 + m * 32 + lane];
            float4 cb = CB4[m * 32 + lane];
            ha.x += cb.x; ha.y += cb.y; ha.z += cb.z; ha.w += cb.w;
#pragma unroll
            for (int i = 0; i < 12; i++) {
                float x = __shfl_sync(0xffffffffu, xv, i);
                float4 wv = W4[i * 64 + m * 32 + lane];
                ha.x += x * wv.x; ha.y += x * wv.y; ha.z += x * wv.z; ha.w += x * wv.w;
            }
            float4 r;
            r.x = fmaxf(ha.x, 0.f); r.y = fmaxf(ha.y, 0.f);
            r.z = fmaxf(ha.z, 0.f); r.w = fmaxf(ha.w, 0.f);
            ((float4*)h1s)[bl * 64 + m * 32 + lane] = r;
        }

#pragma unroll
        for (int o = 16; o; o >>= 1) {
            vp += __shfl_xor_sync(0xffffffffu, vp, o);
            vd += __shfl_xor_sync(0xffffffffu, vd, o);
            vn += __shfl_xor_sync(0xffffffffu, vn, o);
            c0 += __shfl_xor_sync(0xffffffffu, c0, o);
            c1 += __shfl_xor_sync(0xffffffffu, c1, o);
            c2 += __shfl_xor_sync(0xffffffffu, c2, o);
            c3 += __shfl_xor_sync(0xffffffffu, c3, o);
        }
        if (lane == 0) {
            float* rr = redA + bl * 8;
            rr[0] = vp; rr[1] = vd; rr[2] = vn;
            rr[3] = c0; rr[4] = c1; rr[5] = c2; rr[6] = c3;
        }
    }
    __syncthreads();

    if (tid < 8) {
        const int b = gb + tid;
        float* rr = redA + tid * 8;
        float nc = g_NumConn[b];
        float energy = softplusf_(rr[0] + pb2[0]) + 0.05f * nc;
        float delay  = softplusf_(rr[1] + db2[0]);
        float stab   = sigmoidf_(rr[2] + nb2[0]) * 0.36787944117144233f;
        float ent = 0.f;
#pragma unroll
        for (int i = 0; i < 4; i++) {
            float p = rr[3 + i] * (1.f / 256.f);
            if (p > 0.f) ent -= p * log2f(p);
        }
        float dens = nc * (1.f / 65536.f);
        if (dens > 0.f && dens < 1.f) {
            float d = fminf(fmaxf(dens, 1e-12f), 1.f - 1e-12f);
            ent += -d * log2f(d) - (1.f - d) * log2f(1.f - d);
        }
        out[b]            = energy;
        out[4096 + b]     = ent;
        out[2 * 4096 + b] = stab;
        out[4 * 4096 + b] = delay;
    }

    // ---- phase 2: correctness layers 2+3 ----
    const int col = tid & 127;
    const int sub = tid >> 7;
    float acc[8];
#pragma unroll
    for (int i = 0; i < 8; i++) acc[i] = 0.f;

    for (int jc = 0; jc < 4; jc++) {
        __syncthreads();
        const float4* src = (const float4*)(cw2 + jc * 64 * 128);
        float4* dst = (float4*)cw2t;
        for (int i = tid; i < 2048; i += 256) dst[i] = src[i];
        __syncthreads();

        const int jbase = sub * 32;
#pragma unroll
        for (int jj0 = 0; jj0 < 32; jj0 += 4) {
            float w0  = cw2t[(jbase + jj0 + 0) * 128 + col];
            float w1  = cw2t[(jbase + jj0 + 1) * 128 + col];
            float w2v = cw2t[(jbase + jj0 + 2) * 128 + col];
            float w3v = cw2t[(jbase + jj0 + 3) * 128 + col];
#pragma unroll
            for (int blx = 0; blx < 8; blx++) {
                float4 hh = *(const float4*)&h1s[blx * 256 + jc * 64 + jbase + jj0];
                acc[blx] += hh.x * w0 + hh.y * w1 + hh.z * w2v + hh.w * w3v;
            }
        }
    }
    __syncthreads();
    if (sub == 1) {
#pragma unroll
        for (int blx = 0; blx < 8; blx++) pacc[blx * 128 + col] = acc[blx];
    }
    __syncthreads();
    if (sub == 0) {
        const float cb2j = cb2[col], w3 = cw3[col];
#pragma unroll
        for (int blx = 0; blx < 8; blx++) {
            float a = acc[blx] + pacc[blx * 128 + col];
            float h2 = fmaxf(a + cb2j, 0.f);
            float v  = h2 * w3;
#pragma unroll
            for (int o = 16; o; o >>= 1) v += __shfl_xor_sync(0xffffffffu, v, o);
            if (lane == 0) red2[blx * 4 + warp] = v;
        }
    }
    __syncthreads();
    if (tid < 8) {
        float s = red2[tid * 4] + red2[tid * 4 + 1] + red2[tid * 4 + 2] + red2[tid * 4 + 3];
        out[3 * 4096 + gb + tid] = sigmoidf_(s + cb3[0]);
    }
}

// ---------------------------------------------------------------------------
extern "C" void kernel_launch(void* const* d_in, const int* in_sizes, int n_in,
                              void* d_out, int out_size) {
    (void)in_sizes; (void)n_in; (void)out_size;
    const int*   gate_types  = (const int*)  d_in[0];
    const float* connections = (const float*)d_in[1];
    const float* inputs      = (const float*)d_in[2];
    const float* outputs     = (const float*)d_in[3];
    const float* emb         = (const float*)d_in[4];
    const float* pw1 = (const float*)d_in[5];
    const float* pb1 = (const float*)d_in[6];
    const float* pw2 = (const float*)d_in[7];
    const float* pb2 = (const float*)d_in[8];
    const float* dw1 = (const float*)d_in[9];
    const float* db1 = (const float*)d_in[10];
    const float* dw2 = (const float*)d_in[11];
    const float* db2 = (const float*)d_in[12];
    const float* nw1 = (const float*)d_in[13];
    const float* nb1 = (const float*)d_in[14];
    const float* nw2 = (const float*)d_in[15];
    const float* nb2 = (const float*)d_in[16];
    const float* cw1 = (const float*)d_in[17];
    const float* cb1 = (const float*)d_in[18];
    const float* cw2 = (const float*)d_in[19];
    const float* cb2 = (const float*)d_in[20];
    const float* cw3 = (const float*)d_in[21];
    const float* cb3 = (const float*)d_in[22];
    float* out = (float*)d_out;

    const int smemF = (32768 + 1024 + 16) * 4;   // 135232 B
    const int smemD = F_TOT * 4;                 // 61824 B
    cudaFuncSetAttribute(fused_main,      cudaFuncAttributeMaxDynamicSharedMemorySize, smemF);
    cudaFuncSetAttribute(finalize_kernel, cudaFuncAttributeMaxDynamicSharedMemorySize, smemD);

    precompute_P2<<<128, 640>>>(emb, pw1, dw1, nw1, cw1);
    fused_main<<<640, 512, smemF>>>(connections, gate_types);
    finalize_kernel<<<512, 256, smemD>>>(gate_types, inputs, outputs,
                                         pb1, pw2, pb2, db1, dw2, db2,
                                         nb1, nw2, nb2, cw1, cb1,
                                         cw2, cb2, cw3, cb3, out);
}

// round 10
// speedup vs baseline: 1.0519x; 1.0519x over previous
#include <cuda_runtime.h>
#include <stdint.h>
#include <math.h>

// Problem constants
#define Bn 4096
#define Gn 256
#define NCOLS 640

// Scratch (device globals)
__device__ float g_P2tab[20 * 128 * 16 * 32];  // [chunk][pair][combo][c] 5.24 MB
__device__ float g_Hall[Bn * NCOLS];           // 10.5 MB
__device__ float g_NumConn[Bn];

// ---------------------------------------------------------------------------
// Fused precompute: P2[pair, t1*4+t2, c] = emb[t1].W[2p rows] + emb[t2].W[2p+1 rows]
// grid (128 pairs, 2 col-halves), block 320
// ---------------------------------------------------------------------------
__global__ __launch_bounds__(320) void precompute_P2(
        const float* __restrict__ emb,
        const float* __restrict__ pw1, const float* __restrict__ dw1,
        const float* __restrict__ nw1, const float* __restrict__ cw1) {
    __shared__ float embS[128];
    const int p = blockIdx.x;
    const int c = blockIdx.y * 320 + threadIdx.x;
    if (threadIdx.x < 128) embS[threadIdx.x] = emb[threadIdx.x];
    __syncthreads();

    const float* src; int stride;
    if      (c < 128) { src = pw1 + c;         stride = 128; }
    else if (c < 256) { src = dw1 + (c - 128); stride = 128; }
    else if (c < 384) { src = nw1 + (c - 256); stride = 128; }
    else              { src = cw1 + (c - 384); stride = 256; }
    src += (size_t)(2 * p) * 32 * stride;
    const float* src2 = src + 32 * stride;

    float a[4] = {0.f, 0.f, 0.f, 0.f};
    float b[4] = {0.f, 0.f, 0.f, 0.f};
#pragma unroll
    for (int k = 0; k < 32; k += 4) {
        float w0 = src[(k + 0) * stride],  w1 = src[(k + 1) * stride];
        float w2 = src[(k + 2) * stride],  w3 = src[(k + 3) * stride];
        float v0 = src2[(k + 0) * stride], v1 = src2[(k + 1) * stride];
        float v2 = src2[(k + 2) * stride], v3 = src2[(k + 3) * stride];
#pragma unroll
        for (int t = 0; t < 4; t++) {
            a[t] += embS[t*32+k] * w0 + embS[t*32+k+1] * w1 + embS[t*32+k+2] * w2 + embS[t*32+k+3] * w3;
            b[t] += embS[t*32+k] * v0 + embS[t*32+k+1] * v1 + embS[t*32+k+2] * v2 + embS[t*32+k+3] * v3;
        }
    }
    const int ch = c >> 5, cc = c & 31;
    float* base = g_P2tab + ((size_t)(ch * 128 + p) * 16) * 32 + cc;
#pragma unroll
    for (int t1 = 0; t1 < 4; t1++)
#pragma unroll
        for (int t2 = 0; t2 < 4; t2++)
            base[(t1 * 4 + t2) * 32] = a[t1] + b[t2];
}

// ---------------------------------------------------------------------------
// cp.async helpers
// ---------------------------------------------------------------------------
__device__ __forceinline__ void cp_async16(unsigned int saddr, const void* gptr) {
    asm volatile("cp.async.cg.shared.global [%0], [%1], 16;\n" :: "r"(saddr), "l"(gptr));
}
__device__ __forceinline__ void cp_commit() {
    asm volatile("cp.async.commit_group;\n");
}

// ---------------------------------------------------------------------------
// Fused main v3b: 32KB subtiles (16 pairs x 16 combos x 32 cols), double
// buffered via cp.async, 69.7KB smem -> 2 CTAs/SM.
// grid 640 = 64 batch-groups x 10 col-groups; cg<8 blocks own 8 conn rows,
// one row per 2 subtiles; 8 float4 conn loads in flight per w2 iteration
// (full 16384 float4 per row: 2 subtiles x 2 w2 x 8 x 512 threads).
// ---------------------------------------------------------------------------
__global__ __launch_bounds__(512, 2) void fused_main(
        const float* __restrict__ conn, const int* __restrict__ gate_types) {
    extern __shared__ float sC[];
    // layout: tile[2][8192] | tpackS[1024] | ws[16]
    unsigned* tpackS = (unsigned*)(sC + 16384);
    float*    ws     = sC + 16384 + 1024;

    const int tid = threadIdx.x;
    const int grp = blockIdx.x / 10;
    const int cg  = blockIdx.x % 10;
    const int b0  = grp * 64;
    const bool doConn = (cg < 8);

    const unsigned int smemBase = (unsigned int)__cvta_generic_to_shared(sC);

    // prefetch subtile 0 (2048 float4, 4 per thread)
    {
        const float4* srcT = (const float4*)(g_P2tab + ((size_t)(cg * 2 * 128) * 16) * 32);
        unsigned int d = smemBase + tid * 16;
#pragma unroll
        for (int i = 0; i < 4; i++)
            cp_async16(d + i * 512 * 16, srcT + tid + i * 512);
        cp_commit();
    }

    // pack combos: 8 pairs (4 bits each) per u32, 16 words per batch
    for (int i = tid; i < 1024; i += 512) {
        int blc = i >> 4, w = i & 15;
        const int4* gt = (const int4*)(gate_types + (size_t)(b0 + blc) * Gn + w * 16);
        int4 A = gt[0], B4 = gt[1], C = gt[2], D = gt[3];
        unsigned u = 0;
        u |= (unsigned)(A.x * 4 + A.y);
        u |= (unsigned)(A.z * 4 + A.w) << 4;
        u |= (unsigned)(B4.x * 4 + B4.y) << 8;
        u |= (unsigned)(B4.z * 4 + B4.w) << 12;
        u |= (unsigned)(C.x * 4 + C.y) << 16;
        u |= (unsigned)(C.z * 4 + C.w) << 20;
        u |= (unsigned)(D.x * 4 + D.y) << 24;
        u |= (unsigned)(D.z * 4 + D.w) << 28;
        tpackS[i] = u;
    }

    const int bl = tid >> 3;   // local batch 0..63
    const int c4 = tid & 7;    // float4 col slot

    float ax = 0.f, ay = 0.f, az = 0.f, aw = 0.f;
    float rsum = 0.f;

#pragma unroll
    for (int s = 0; s < 16; s++) {
        // prefetch next subtile into the other buffer
        if (s < 15) {
            const int ns = s + 1;
            const int chunk  = cg * 2 + (ns >> 3);
            const int pair16 = ns & 7;
            const float4* srcT = (const float4*)(g_P2tab +
                                 ((size_t)(chunk * 128 + pair16 * 16) * 16) * 32);
            unsigned int d = smemBase + (ns & 1) * 32768 + tid * 16;
#pragma unroll
            for (int i = 0; i < 4; i++)
                cp_async16(d + i * 512 * 16, srcT + tid + i * 512);
            cp_commit();
            asm volatile("cp.async.wait_group 1;\n");
        } else {
            asm volatile("cp.async.wait_group 0;\n");
        }
        __syncthreads();  // current tile visible; also covers tpackS on s=0

        const float* tileS = sC + (s & 1) * 8192;
        const int pair16 = s & 7;

        const int row = b0 + ((cg < 8) ? cg : 0) * 8 + (s >> 1);
        // half-row window of 8192 float4 for this subtile
        const float4* cp4 = (const float4*)conn + ((size_t)row << 14)
                          + (s & 1) * 8192 + tid;

#pragma unroll
        for (int w2 = 0; w2 < 2; w2++) {
            const unsigned word = tpackS[bl * 16 + pair16 * 2 + w2];

            float4 q0, q1, q2, q3, q4, q5, q6, q7;
            if (doConn) {
                q0 = cp4[(w2 * 8 + 0) * 512];
                q1 = cp4[(w2 * 8 + 1) * 512];
                q2 = cp4[(w2 * 8 + 2) * 512];
                q3 = cp4[(w2 * 8 + 3) * 512];
                q4 = cp4[(w2 * 8 + 4) * 512];
                q5 = cp4[(w2 * 8 + 5) * 512];
                q6 = cp4[(w2 * 8 + 6) * 512];
                q7 = cp4[(w2 * 8 + 7) * 512];
            } else {
                q0 = q1 = q2 = q3 = q4 = q5 = q6 = q7 = make_float4(0.f, 0.f, 0.f, 0.f);
            }
#pragma unroll
            for (int i = 0; i < 8; i++) {
                int combo = (int)((word >> (i * 4)) & 15u);
                const float4 v = *(const float4*)&tileS[((w2 * 8 + i) * 16 + combo) * 32 + c4 * 4];
                ax += v.x; ay += v.y; az += v.z; aw += v.w;
            }
            rsum += (((q0.x + q0.y) + (q0.z + q0.w)) + ((q1.x + q1.y) + (q1.z + q1.w)))
                  + (((q2.x + q2.y) + (q2.z + q2.w)) + ((q3.x + q3.y) + (q3.z + q3.w)))
                  + (((q4.x + q4.y) + (q4.z + q4.w)) + ((q5.x + q5.y) + (q5.z + q5.w)))
                  + (((q6.x + q6.y) + (q6.z + q6.w)) + ((q7.x + q7.y) + (q7.z + q7.w)));
        }

        // Hall writes at end of each chunk
        if (s == 7) {
            float4 rr; rr.x = ax; rr.y = ay; rr.z = az; rr.w = aw;
            *(float4*)(g_Hall + (size_t)(b0 + bl) * NCOLS + (cg * 2) * 32 + c4 * 4) = rr;
            ax = ay = az = aw = 0.f;
        }
        if (s == 15) {
            float4 rr; rr.x = ax; rr.y = ay; rr.z = az; rr.w = aw;
            *(float4*)(g_Hall + (size_t)(b0 + bl) * NCOLS + (cg * 2 + 1) * 32 + c4 * 4) = rr;
        }

        // conn row finished every second subtile
        if ((s & 1) && doConn) {
#pragma unroll
            for (int o = 16; o; o >>= 1) rsum += __shfl_xor_sync(0xffffffffu, rsum, o);
            if ((tid & 31) == 0) ws[tid >> 5] = rsum;
        }
        __syncthreads();  // ws ready; buffer reads done before next prefetch
        if ((s & 1) && doConn && tid == 0) {
            float t = 0.f;
#pragma unroll
            for (int i = 0; i < 16; i++) t += ws[i];
            g_NumConn[row] = t;
        }
        if (s & 1) rsum = 0.f;
    }
}

// ---------------------------------------------------------------------------
// Finalize v2: 512 blocks x 256 threads, 8 batches/block, vectorized.
// ---------------------------------------------------------------------------
__device__ __forceinline__ float softplusf_(float x) {
    return (x > 20.f) ? x : log1pf(expf(x));
}
__device__ __forceinline__ float sigmoidf_(float x) {
    return 1.f / (1.f + expf(-x));
}

// smem layout (floats)
#define F_H1S   0        // 2048 (8 x 256)
#define F_CW2T  2048     // 8192
#define F_BIAS  10240    // 768
#define F_CB1   11008    // 256
#define F_WIN   11264    // 3072
#define F_REDA  14336    // 64 (8 x 8)
#define F_PACC  14400    // 1024 (8 x 128)
#define F_RED2  15424    // 32
#define F_TOT   15456

__global__ __launch_bounds__(256) void finalize_kernel(
        const int* __restrict__ gate_types,
        const float* __restrict__ inputs,
        const float* __restrict__ outputs,
        const float* __restrict__ pb1, const float* __restrict__ pw2, const float* __restrict__ pb2,
        const float* __restrict__ db1, const float* __restrict__ dw2, const float* __restrict__ db2,
        const float* __restrict__ nb1, const float* __restrict__ nw2, const float* __restrict__ nb2,
        const float* __restrict__ cw1, const float* __restrict__ cb1,
        const float* __restrict__ cw2, const float* __restrict__ cb2,
        const float* __restrict__ cw3, const float* __restrict__ cb3,
        float* __restrict__ out) {
    extern __shared__ float sD[];
    float* h1s   = sD + F_H1S;
    float* cw2t  = sD + F_CW2T;
    float* biasS = sD + F_BIAS;
    float* cb1S  = sD + F_CB1;
    float* winS  = sD + F_WIN;
    float* redA  = sD + F_REDA;
    float* pacc  = sD + F_PACC;
    float* red2  = sD + F_RED2;

    const int tid  = threadIdx.x;
    const int lane = tid & 31, warp = tid >> 5;
    const int gb   = blockIdx.x * 8;

    if (tid < 128) {
        biasS[tid]       = pb1[tid];
        biasS[128 + tid] = db1[tid];
        biasS[256 + tid] = nb1[tid];
        biasS[384 + tid] = pw2[tid];
        biasS[512 + tid] = dw2[tid];
        biasS[640 + tid] = nw2[tid];
    }
    cb1S[tid] = cb1[tid];
    const float* winsrc = cw1 + 8192 * 256;
    for (int i = tid; i < 3072; i += 256) winS[i] = winsrc[i];
    __syncthreads();

    // ---- phase 1: warp per batch, all float4 ----
    {
        const int bl = warp;           // 0..7
        const int b  = gb + bl;
        const float4* H4  = (const float4*)(g_Hall + (size_t)b * NCOLS);
        const float4* B4  = (const float4*)biasS;
        const float4* CB4 = (const float4*)cb1S;
        const float4* W4  = (const float4*)winS;

        float4 h, bb, ww;
        h = H4[lane];        bb = B4[lane];        ww = B4[96 + lane];
        float vp = fmaxf(h.x + bb.x, 0.f) * ww.x + fmaxf(h.y + bb.y, 0.f) * ww.y
                 + fmaxf(h.z + bb.z, 0.f) * ww.z + fmaxf(h.w + bb.w, 0.f) * ww.w;
        h = H4[32 + lane];   bb = B4[32 + lane];   ww = B4[128 + lane];
        float vd = fmaxf(h.x + bb.x, 0.f) * ww.x + fmaxf(h.y + bb.y, 0.f) * ww.y
                 + fmaxf(h.z + bb.z, 0.f) * ww.z + fmaxf(h.w + bb.w, 0.f) * ww.w;
        h = H4[64 + lane];   bb = B4[64 + lane];   ww = B4[160 + lane];
        float vn = fmaxf(h.x + bb.x, 0.f) * ww.x + fmaxf(h.y + bb.y, 0.f) * ww.y
                 + fmaxf(h.z + bb.z, 0.f) * ww.z + fmaxf(h.w + bb.w, 0.f) * ww.w;

        const int4* tq = (const int4*)(gate_types + (size_t)b * Gn);
        int4 ta = tq[lane * 2], tb = tq[lane * 2 + 1];
        float c0 = (float)((ta.x == 0) + (ta.y == 0) + (ta.z == 0) + (ta.w == 0)
                         + (tb.x == 0) + (tb.y == 0) + (tb.z == 0) + (tb.w == 0));
        float c1 = (float)((ta.x == 1) + (ta.y == 1) + (ta.z == 1) + (ta.w == 1)
                         + (tb.x == 1) + (tb.y == 1) + (tb.z == 1) + (tb.w == 1));
        float c2 = (float)((ta.x == 2) + (ta.y == 2) + (ta.z == 2) + (ta.w == 2)
                         + (tb.x == 2) + (tb.y == 2) + (tb.z == 2) + (tb.w == 2));
        float c3 = (float)((ta.x == 3) + (ta.y == 3) + (ta.z == 3) + (ta.w == 3)
                         + (tb.x == 3) + (tb.y == 3) + (tb.z == 3) + (tb.w == 3));

        float xv = 0.f;
        if (lane < 8)       xv = inputs[b * 8 + lane];
        else if (lane < 12) xv = outputs[b * 4 + lane - 8];

#pragma unroll
        for (int m = 0; m < 2; m++) {
            float4 ha = H4[96 + m * 32 + lane];
            float4 cb = CB4[m * 32 + lane];
            ha.x += cb.x; ha.y += cb.y; ha.z += cb.z; ha.w += cb.w;
#pragma unroll
            for (int i = 0; i < 12; i++) {
                float x = __shfl_sync(0xffffffffu, xv, i);
                float4 wv = W4[i * 64 + m * 32 + lane];
                ha.x += x * wv.x; ha.y += x * wv.y; ha.z += x * wv.z; ha.w += x * wv.w;
            }
            float4 r;
            r.x = fmaxf(ha.x, 0.f); r.y = fmaxf(ha.y, 0.f);
            r.z = fmaxf(ha.z, 0.f); r.w = fmaxf(ha.w, 0.f);
            ((float4*)h1s)[bl * 64 + m * 32 + lane] = r;
        }

#pragma unroll
        for (int o = 16; o; o >>= 1) {
            vp += __shfl_xor_sync(0xffffffffu, vp, o);
            vd += __shfl_xor_sync(0xffffffffu, vd, o);
            vn += __shfl_xor_sync(0xffffffffu, vn, o);
            c0 += __shfl_xor_sync(0xffffffffu, c0, o);
            c1 += __shfl_xor_sync(0xffffffffu, c1, o);
            c2 += __shfl_xor_sync(0xffffffffu, c2, o);
            c3 += __shfl_xor_sync(0xffffffffu, c3, o);
        }
        if (lane == 0) {
            float* rr = redA + bl * 8;
            rr[0] = vp; rr[1] = vd; rr[2] = vn;
            rr[3] = c0; rr[4] = c1; rr[5] = c2; rr[6] = c3;
        }
    }
    __syncthreads();

    if (tid < 8) {
        const int b = gb + tid;
        float* rr = redA + tid * 8;
        float nc = g_NumConn[b];
        float energy = softplusf_(rr[0] + pb2[0]) + 0.05f * nc;
        float delay  = softplusf_(rr[1] + db2[0]);
        float stab   = sigmoidf_(rr[2] + nb2[0]) * 0.36787944117144233f;
        float ent = 0.f;
#pragma unroll
        for (int i = 0; i < 4; i++) {
            float p = rr[3 + i] * (1.f / 256.f);
            if (p > 0.f) ent -= p * log2f(p);
        }
        float dens = nc * (1.f / 65536.f);
        if (dens > 0.f && dens < 1.f) {
            float d = fminf(fmaxf(dens, 1e-12f), 1.f - 1e-12f);
            ent += -d * log2f(d) - (1.f - d) * log2f(1.f - d);
        }
        out[b]            = energy;
        out[4096 + b]     = ent;
        out[2 * 4096 + b] = stab;
        out[4 * 4096 + b] = delay;
    }

    // ---- phase 2: correctness layers 2+3 ----
    const int col = tid & 127;
    const int sub = tid >> 7;
    float acc[8];
#pragma unroll
    for (int i = 0; i < 8; i++) acc[i] = 0.f;

    for (int jc = 0; jc < 4; jc++) {
        __syncthreads();
        const float4* src = (const float4*)(cw2 + jc * 64 * 128);
        float4* dst = (float4*)cw2t;
        for (int i = tid; i < 2048; i += 256) dst[i] = src[i];
        __syncthreads();

        const int jbase = sub * 32;
#pragma unroll
        for (int jj0 = 0; jj0 < 32; jj0 += 4) {
            float w0  = cw2t[(jbase + jj0 + 0) * 128 + col];
            float w1  = cw2t[(jbase + jj0 + 1) * 128 + col];
            float w2v = cw2t[(jbase + jj0 + 2) * 128 + col];
            float w3v = cw2t[(jbase + jj0 + 3) * 128 + col];
#pragma unroll
            for (int blx = 0; blx < 8; blx++) {
                float4 hh = *(const float4*)&h1s[blx * 256 + jc * 64 + jbase + jj0];
                acc[blx] += hh.x * w0 + hh.y * w1 + hh.z * w2v + hh.w * w3v;
            }
        }
    }
    __syncthreads();
    if (sub == 1) {
#pragma unroll
        for (int blx = 0; blx < 8; blx++) pacc[blx * 128 + col] = acc[blx];
    }
    __syncthreads();
    if (sub == 0) {
        const float cb2j = cb2[col], w3 = cw3[col];
#pragma unroll
        for (int blx = 0; blx < 8; blx++) {
            float a = acc[blx] + pacc[blx * 128 + col];
            float h2 = fmaxf(a + cb2j, 0.f);
            float v  = h2 * w3;
#pragma unroll
            for (int o = 16; o; o >>= 1) v += __shfl_xor_sync(0xffffffffu, v, o);
            if (lane == 0) red2[blx * 4 + warp] = v;
        }
    }
    __syncthreads();
    if (tid < 8) {
        float s = red2[tid * 4] + red2[tid * 4 + 1] + red2[tid * 4 + 2] + red2[tid * 4 + 3];
        out[3 * 4096 + gb + tid] = sigmoidf_(s + cb3[0]);
    }
}

// ---------------------------------------------------------------------------
extern "C" void kernel_launch(void* const* d_in, const int* in_sizes, int n_in,
                              void* d_out, int out_size) {
    (void)in_sizes; (void)n_in; (void)out_size;
    const int*   gate_types  = (const int*)  d_in[0];
    const float* connections = (const float*)d_in[1];
    const float* inputs      = (const float*)d_in[2];
    const float* outputs     = (const float*)d_in[3];
    const float* emb         = (const float*)d_in[4];
    const float* pw1 = (const float*)d_in[5];
    const float* pb1 = (const float*)d_in[6];
    const float* pw2 = (const float*)d_in[7];
    const float* pb2 = (const float*)d_in[8];
    const float* dw1 = (const float*)d_in[9];
    const float* db1 = (const float*)d_in[10];
    const float* dw2 = (const float*)d_in[11];
    const float* db2 = (const float*)d_in[12];
    const float* nw1 = (const float*)d_in[13];
    const float* nb1 = (const float*)d_in[14];
    const float* nw2 = (const float*)d_in[15];
    const float* nb2 = (const float*)d_in[16];
    const float* cw1 = (const float*)d_in[17];
    const float* cb1 = (const float*)d_in[18];
    const float* cw2 = (const float*)d_in[19];
    const float* cb2 = (const float*)d_in[20];
    const float* cw3 = (const float*)d_in[21];
    const float* cb3 = (const float*)d_in[22];
    float* out = (float*)d_out;

    const int smemF = (16384 + 1024 + 16) * 4;   // 69696 B -> 2 CTAs/SM
    const int smemD = F_TOT * 4;                 // 61824 B
    cudaFuncSetAttribute(fused_main,      cudaFuncAttributeMaxDynamicSharedMemorySize, smemF);
    cudaFuncSetAttribute(finalize_kernel, cudaFuncAttributeMaxDynamicSharedMemorySize, smemD);

    precompute_P2<<<dim3(128, 2), 320>>>(emb, pw1, dw1, nw1, cw1);
    fused_main<<<640, 512, smemF>>>(connections, gate_types);
    finalize_kernel<<<512, 256, smemD>>>(gate_types, inputs, outputs,
                                         pb1, pw2, pb2, db1, dw2, db2,
                                         nb1, nw2, nb2, cw1, cb1,
                                         cw2, cb2, cw3, cb3, out);
}